// round 2
// baseline (speedup 1.0000x reference)
#include <cuda_runtime.h>
#include <cuda_bf16.h>
#include <math.h>

// Problem constants
#define T_SEQ 4096
#define DIM 1024
#define NHEAD 16
#define HDIM 64
#define HD3 3072          // 3*NHEAD*HDIM
#define RMS_EPS 1e-6f

// ---------------------------------------------------------------------------
// Scratch (device globals; no allocation allowed)
// ---------------------------------------------------------------------------
__device__ float g_qkv[T_SEQ * HD3];              // [t][f]
__device__ float g_Q[NHEAD * T_SEQ * HDIM];       // [h][t][d]
__device__ float g_K[NHEAD * T_SEQ * HDIM];
__device__ float g_V[NHEAD * T_SEQ * HDIM];
__device__ float g_Y[T_SEQ * DIM];                // attention out, [t][h*64+d]
__device__ float g_cos[T_SEQ * 32];
__device__ float g_sin[T_SEQ * 32];

// ---------------------------------------------------------------------------
// RoPE tables (fp64 for accuracy vs fp32 JAX reference)
// ---------------------------------------------------------------------------
__global__ void rope_tables_kernel(float* ct, float* st) {
    int t = blockIdx.x;
    int l = threadIdx.x;     // 0..31
    double c = 1.0, s = 0.0;
    if (l < 16) {
        double freq = exp(-((double)l / 15.0) * log(1024.0));
        double th = (double)t * freq;
        c = cos(th);
        s = sin(th);
    }
    ct[t * 32 + l] = (float)c;
    st[t * 32 + l] = (float)s;
}

// ---------------------------------------------------------------------------
// TN GEMM: C[m][n] = sum_k A[m*K+k] * B[n*K+k]
// 128x128 tile, KT=8, 256 threads, 8x8 per thread.
// M,N multiples of 128; K multiple of 8.
// ---------------------------------------------------------------------------
__global__ void __launch_bounds__(256) gemm_tn_kernel(
    const float* __restrict__ A, const float* __restrict__ B,
    float* __restrict__ C, int M, int N, int K)
{
    __shared__ float As[8][128];
    __shared__ float Bs[8][128];

    int bm = blockIdx.y * 128;
    int bn = blockIdx.x * 128;
    int tid = threadIdx.x;
    int tx = tid & 15;       // 0..15  -> n block of 8
    int ty = tid >> 4;       // 0..15  -> m block of 8

    int lr = tid >> 1;           // 0..127 row within tile
    int lk = (tid & 1) * 4;      // 0 or 4

    const float* Ap = A + (size_t)(bm + lr) * K + lk;
    const float* Bp = B + (size_t)(bn + lr) * K + lk;

    float acc[8][8];
#pragma unroll
    for (int i = 0; i < 8; i++)
#pragma unroll
        for (int j = 0; j < 8; j++) acc[i][j] = 0.0f;

    for (int k0 = 0; k0 < K; k0 += 8) {
        float4 va = *(const float4*)(Ap + k0);
        float4 vb = *(const float4*)(Bp + k0);
        __syncthreads();
        As[lk + 0][lr] = va.x; As[lk + 1][lr] = va.y;
        As[lk + 2][lr] = va.z; As[lk + 3][lr] = va.w;
        Bs[lk + 0][lr] = vb.x; Bs[lk + 1][lr] = vb.y;
        Bs[lk + 2][lr] = vb.z; Bs[lk + 3][lr] = vb.w;
        __syncthreads();

#pragma unroll
        for (int k = 0; k < 8; k++) {
            float a[8], b[8];
#pragma unroll
            for (int i = 0; i < 8; i++) a[i] = As[k][ty * 8 + i];
#pragma unroll
            for (int j = 0; j < 8; j++) b[j] = Bs[k][tx * 8 + j];
#pragma unroll
            for (int i = 0; i < 8; i++)
#pragma unroll
                for (int j = 0; j < 8; j++) acc[i][j] += a[i] * b[j];
        }
    }

#pragma unroll
    for (int i = 0; i < 8; i++) {
        float* Cr = C + (size_t)(bm + ty * 8 + i) * N + bn + tx * 8;
#pragma unroll
        for (int j = 0; j < 8; j++) Cr[j] = acc[i][j];
    }
}

// ---------------------------------------------------------------------------
// Post-QKV: RMSNorm(q,k) -> RoPE(q,k), v *= lambdas[0]. One warp per (t,h).
// Writes [h][t][d] layouts for attention.
// ---------------------------------------------------------------------------
__global__ void __launch_bounds__(256) qkv_post_kernel(const float* __restrict__ lambdas) {
    int w = (blockIdx.x * blockDim.x + threadIdx.x) >> 5;   // 0 .. T*H-1
    int lane = threadIdx.x & 31;
    int t = w >> 4;
    int h = w & 15;

    const float* base = g_qkv + (size_t)t * HD3 + h * HDIM;
    float c = g_cos[t * 32 + lane];
    float s = g_sin[t * 32 + lane];

    // ---- Q ----
    {
        float x1 = base[lane];
        float x2 = base[32 + lane];
        float ss = x1 * x1 + x2 * x2;
#pragma unroll
        for (int off = 16; off; off >>= 1) ss += __shfl_xor_sync(0xffffffffu, ss, off);
        float rn = 1.0f / sqrtf(ss * (1.0f / 64.0f) + RMS_EPS);
        x1 *= rn; x2 *= rn;
        float y1 = x1 * c + x2 * s;
        float y2 = x2 * c - x1 * s;
        float* out = g_Q + ((size_t)h * T_SEQ + t) * HDIM;
        out[lane] = y1;
        out[32 + lane] = y2;
    }
    // ---- K ----
    {
        float x1 = base[1024 + lane];
        float x2 = base[1024 + 32 + lane];
        float ss = x1 * x1 + x2 * x2;
#pragma unroll
        for (int off = 16; off; off >>= 1) ss += __shfl_xor_sync(0xffffffffu, ss, off);
        float rn = 1.0f / sqrtf(ss * (1.0f / 64.0f) + RMS_EPS);
        x1 *= rn; x2 *= rn;
        float y1 = x1 * c + x2 * s;
        float y2 = x2 * c - x1 * s;
        float* out = g_K + ((size_t)h * T_SEQ + t) * HDIM;
        out[lane] = y1;
        out[32 + lane] = y2;
    }
    // ---- V ----
    {
        float lam = lambdas[0];
        float* out = g_V + ((size_t)h * T_SEQ + t) * HDIM;
        out[lane] = lam * base[2048 + lane];
        out[32 + lane] = lam * base[2048 + 32 + lane];
    }
}

// ---------------------------------------------------------------------------
// Causal flash attention, fp32. 64x64 tiles.
// 256 threads: each owns rows {rw, rw+32} (rw = tid>>3) and cols l8+8*jj.
// Online softmax; p broadcast across 8-lane groups via shfl.
// Smem exactly 48 KB (static): Kst uses a rotation swizzle instead of padding.
// ---------------------------------------------------------------------------
// Kst swizzle: logical (d, c) stored at d*64 + ((c + d*8) & 63).
// For fixed d, distinct c -> distinct banks (rotation is a bijection), so the
// 8-lane read of consecutive c stays conflict-free; writes (fixed c, d range)
// also spread across banks.
__device__ __forceinline__ int kswz(int d, int c) {
    return d * 64 + ((c + d * 8) & 63);
}

__global__ void __launch_bounds__(256) flash_attn_kernel() {
    __shared__ float Qs[64 * 64];    // [r][d] row-major
    __shared__ float Kst[64 * 64];   // swizzled [d][c]
    __shared__ float Vs[64 * 64];    // [c][d] row-major

    int qt = blockIdx.x;        // q tile, 0..63
    int h = blockIdx.y;
    int tid = threadIdx.x;
    int lane = tid & 31;
    int l8 = tid & 7;
    int rw = tid >> 3;          // 0..31
    const float scale = 0.125f;
    const float NEG_INF = -__int_as_float(0x7f800000);

    const float* Qh = g_Q + ((size_t)h * T_SEQ + qt * 64) * HDIM;
    const float* Kh = g_K + (size_t)h * T_SEQ * HDIM;
    const float* Vh = g_V + (size_t)h * T_SEQ * HDIM;

#pragma unroll
    for (int i = 0; i < 16; i++) {
        int idx = tid + 256 * i;
        int rr = idx >> 6, d = idx & 63;
        Qs[rr * 64 + d] = Qh[rr * 64 + d];
    }

    float o0[8], o1[8];
#pragma unroll
    for (int j = 0; j < 8; j++) { o0[j] = 0.0f; o1[j] = 0.0f; }
    float m0 = NEG_INF, m1 = NEG_INF, l0 = 0.0f, l1 = 0.0f;

    for (int kt = 0; kt <= qt; kt++) {
        __syncthreads();
#pragma unroll
        for (int i = 0; i < 16; i++) {
            int idx = tid + 256 * i;
            int cc = idx >> 6, d = idx & 63;
            Kst[kswz(d, cc)] = Kh[(size_t)(kt * 64 + cc) * 64 + d];
            Vs[cc * 64 + d] = Vh[(size_t)(kt * 64 + cc) * 64 + d];
        }
        __syncthreads();

        float s0[8], s1[8];
#pragma unroll
        for (int j = 0; j < 8; j++) { s0[j] = 0.0f; s1[j] = 0.0f; }

#pragma unroll 16
        for (int d = 0; d < 64; d++) {
            float q0 = Qs[rw * 64 + d];
            float q1 = Qs[(rw + 32) * 64 + d];
#pragma unroll
            for (int jj = 0; jj < 8; jj++) {
                float kv = Kst[kswz(d, jj * 8 + l8)];
                s0[jj] += q0 * kv;
                s1[jj] += q1 * kv;
            }
        }

        bool diag = (kt == qt);
        float tm0 = NEG_INF, tm1 = NEG_INF;
#pragma unroll
        for (int jj = 0; jj < 8; jj++) {
            int c = jj * 8 + l8;
            float v0 = s0[jj] * scale;
            float v1 = s1[jj] * scale;
            if (diag) {
                if (c > rw) v0 = NEG_INF;
                if (c > rw + 32) v1 = NEG_INF;
            }
            s0[jj] = v0; s1[jj] = v1;
            tm0 = fmaxf(tm0, v0);
            tm1 = fmaxf(tm1, v1);
        }
#pragma unroll
        for (int off = 1; off < 8; off <<= 1) {
            tm0 = fmaxf(tm0, __shfl_xor_sync(0xffffffffu, tm0, off));
            tm1 = fmaxf(tm1, __shfl_xor_sync(0xffffffffu, tm1, off));
        }
        float nm0 = fmaxf(m0, tm0);
        float nm1 = fmaxf(m1, tm1);
        float cor0 = expf(m0 - nm0);
        float cor1 = expf(m1 - nm1);

        float ps0 = 0.0f, ps1 = 0.0f;
#pragma unroll
        for (int jj = 0; jj < 8; jj++) {
            float p0 = expf(s0[jj] - nm0);
            float p1 = expf(s1[jj] - nm1);
            s0[jj] = p0; s1[jj] = p1;
            ps0 += p0; ps1 += p1;
        }
#pragma unroll
        for (int off = 1; off < 8; off <<= 1) {
            ps0 += __shfl_xor_sync(0xffffffffu, ps0, off);
            ps1 += __shfl_xor_sync(0xffffffffu, ps1, off);
        }
        l0 = l0 * cor0 + ps0;
        l1 = l1 * cor1 + ps1;
#pragma unroll
        for (int jj = 0; jj < 8; jj++) { o0[jj] *= cor0; o1[jj] *= cor1; }
        m0 = nm0; m1 = nm1;

        int lbase = lane & ~7;
#pragma unroll
        for (int c = 0; c < 64; c++) {
            float p0 = __shfl_sync(0xffffffffu, s0[c >> 3], lbase + (c & 7));
            float p1 = __shfl_sync(0xffffffffu, s1[c >> 3], lbase + (c & 7));
#pragma unroll
            for (int jj = 0; jj < 8; jj++) {
                float vv = Vs[c * 64 + jj * 8 + l8];
                o0[jj] += p0 * vv;
                o1[jj] += p1 * vv;
            }
        }
    }

    float inv0 = 1.0f / l0;
    float inv1 = 1.0f / l1;
    int t0 = qt * 64 + rw;
    int t1 = t0 + 32;
#pragma unroll
    for (int jj = 0; jj < 8; jj++) {
        g_Y[(size_t)t0 * DIM + h * HDIM + jj * 8 + l8] = o0[jj] * inv0;
        g_Y[(size_t)t1 * DIM + h * HDIM + jj * 8 + l8] = o1[jj] * inv1;
    }
}

// ---------------------------------------------------------------------------
// Launch
// ---------------------------------------------------------------------------
extern "C" void kernel_launch(void* const* d_in, const int* in_sizes, int n_in,
                              void* d_out, int out_size)
{
    const float* x = (const float*)d_in[0];        // [1,4096,1024]
    const float* qkv_w = (const float*)d_in[1];    // [3072,1024]
    const float* lambdas = (const float*)d_in[2];  // [1]
    const float* proj_w = (const float*)d_in[3];   // [1024,1024]
    float* out = (float*)d_out;

    float *p_qkv, *p_Y, *p_cos, *p_sin;
    cudaGetSymbolAddress((void**)&p_qkv, g_qkv);
    cudaGetSymbolAddress((void**)&p_Y, g_Y);
    cudaGetSymbolAddress((void**)&p_cos, g_cos);
    cudaGetSymbolAddress((void**)&p_sin, g_sin);

    // 0) RoPE tables
    rope_tables_kernel<<<T_SEQ, 32>>>(p_cos, p_sin);

    // 1) QKV GEMM: [4096,1024] x [3072,1024]^T -> [4096,3072]
    {
        dim3 grid(HD3 / 128, T_SEQ / 128);
        gemm_tn_kernel<<<grid, 256>>>(x, qkv_w, p_qkv, T_SEQ, HD3, DIM);
    }

    // 2) RMSNorm + RoPE + lambda*v
    {
        int warps = T_SEQ * NHEAD;                 // 65536 warps
        qkv_post_kernel<<<warps * 32 / 256, 256>>>(lambdas);
    }

    // 3) Causal flash attention (48 KB static smem, no attribute call needed)
    {
        dim3 grid(T_SEQ / 64, NHEAD);
        flash_attn_kernel<<<grid, 256>>>();
    }

    // 4) Proj GEMM: [4096,1024] x [1024,1024]^T -> out
    {
        dim3 grid(DIM / 128, T_SEQ / 128);
        gemm_tn_kernel<<<grid, 256>>>(p_Y, proj_w, out, T_SEQ, DIM, DIM);
    }
}

// round 4
// speedup vs baseline: 1.2035x; 1.2035x over previous
#include <cuda_runtime.h>
#include <cuda_bf16.h>
#include <math.h>
#include <stdint.h>

// Problem constants
#define T_SEQ 4096
#define DIM 1024
#define NHEAD 16
#define HDIM 64
#define HD3 3072          // 3*NHEAD*HDIM
#define RMS_EPS 1e-6f

// ---------------------------------------------------------------------------
// Scratch (device globals; no allocation allowed)
// ---------------------------------------------------------------------------
__device__ float g_qkv[T_SEQ * HD3];              // [t][f]
__device__ float g_Q[NHEAD * T_SEQ * HDIM];       // [h][t][d]
__device__ float g_K[NHEAD * T_SEQ * HDIM];
__device__ float g_V[NHEAD * T_SEQ * HDIM];
__device__ float g_Y[T_SEQ * DIM];                // attention out, [t][h*64+d]
__device__ float g_cos[T_SEQ * 32];
__device__ float g_sin[T_SEQ * 32];

// ===========================================================================
// mma.sync helpers (baseline PTX, works on sm_100 without 'a' suffix)
// ===========================================================================
#define LDSM4(R0, R1, R2, R3, ADDR) \
    asm volatile("ldmatrix.sync.aligned.m8n8.x4.shared.b16 {%0,%1,%2,%3}, [%4];" \
        : "=r"(R0), "=r"(R1), "=r"(R2), "=r"(R3) : "r"(ADDR))

#define MMA16816(D, A0, A1, A2, A3, B0, B1) \
    asm volatile("mma.sync.aligned.m16n8k16.row.col.f32.bf16.bf16.f32 " \
        "{%0,%1,%2,%3}, {%4,%5,%6,%7}, {%8,%9}, {%0,%1,%2,%3};" \
        : "+f"((D)[0]), "+f"((D)[1]), "+f"((D)[2]), "+f"((D)[3]) \
        : "r"(A0), "r"(A1), "r"(A2), "r"(A3), "r"(B0), "r"(B1))

__device__ __forceinline__ uint32_t smem_addr_u32(const void* p) {
    return (uint32_t)__cvta_generic_to_shared(p);
}

__device__ __forceinline__ uint32_t pack_bf2(__nv_bfloat16 a, __nv_bfloat16 b) {
    union { __nv_bfloat162 v; uint32_t u; } t;
    t.v = __nv_bfloat162(a, b);   // .x = low 16 bits
    return t.u;
}

// Split a float4 into hi/lo bf16 and store 4 halves to each of two smem tiles.
__device__ __forceinline__ void split_store(__nv_bfloat16* hi_t, __nv_bfloat16* lo_t,
                                            int off_halves, float4 v) {
    __nv_bfloat16 h0 = __float2bfloat16_rn(v.x);
    __nv_bfloat16 h1 = __float2bfloat16_rn(v.y);
    __nv_bfloat16 h2 = __float2bfloat16_rn(v.z);
    __nv_bfloat16 h3 = __float2bfloat16_rn(v.w);
    __nv_bfloat16 l0 = __float2bfloat16_rn(v.x - __bfloat162float(h0));
    __nv_bfloat16 l1 = __float2bfloat16_rn(v.y - __bfloat162float(h1));
    __nv_bfloat16 l2 = __float2bfloat16_rn(v.z - __bfloat162float(h2));
    __nv_bfloat16 l3 = __float2bfloat16_rn(v.w - __bfloat162float(h3));
    *(uint2*)((char*)hi_t + off_halves * 2) = make_uint2(pack_bf2(h0, h1), pack_bf2(h2, h3));
    *(uint2*)((char*)lo_t + off_halves * 2) = make_uint2(pack_bf2(l0, l1), pack_bf2(l2, l3));
}

// ===========================================================================
// bf16-split TN GEMM via mma.sync: C[m][n] = sum_k A[m][k]*B[n][k]
// 128x128 CTA tile, 8 warps (warp tile 64x32), K-chunks of 32.
// D <- Ah*Bh + Ah*Bl + Al*Bh  (fp32 accumulators in registers)
// Smem rows padded to 40 halves (80B) -> conflict-free ldmatrix.
// ===========================================================================
#define LDSS 40   // smem row stride in halves

__global__ void __launch_bounds__(256, 1) gemm_mma_kernel(
    const float* __restrict__ A, const float* __restrict__ B,
    float* __restrict__ C, int N, int K)
{
    __shared__ __align__(16) __nv_bfloat16 sAh[128 * LDSS];
    __shared__ __align__(16) __nv_bfloat16 sAl[128 * LDSS];
    __shared__ __align__(16) __nv_bfloat16 sBh[128 * LDSS];
    __shared__ __align__(16) __nv_bfloat16 sBl[128 * LDSS];

    int tid = threadIdx.x;
    int wid = tid >> 5;
    int lane = tid & 31;
    int bm = blockIdx.y * 128;
    int bn = blockIdx.x * 128;
    int wm = (wid & 1) * 64;       // warp m offset within tile
    int wn = (wid >> 1) * 32;      // warp n offset within tile
    int g = lane >> 2;             // group id (row within fragment)
    int tig = lane & 3;            // thread in group

    float acc[4][4][4];
#pragma unroll
    for (int mt = 0; mt < 4; mt++)
#pragma unroll
        for (int nt = 0; nt < 4; nt++)
#pragma unroll
            for (int r = 0; r < 4; r++) acc[mt][nt][r] = 0.0f;

    // ldmatrix lane addressing (precomputed offsets in halves)
    int arow = wm + (lane & 15);
    int akoff = (lane >> 4) * 8;           // +ks*16 later
    int brow = wn + (lane & 7) + ((lane >> 4) & 1) * 8;
    int bkoff = ((lane >> 3) & 1) * 8;

    const int NCHUNK = K / 32;
    for (int ch = 0; ch < NCHUNK; ch++) {
        int k0 = ch * 32;
        __syncthreads();
#pragma unroll
        for (int i = 0; i < 4; i++) {
            int idx = tid + 256 * i;       // 0..1023
            int r = idx >> 3;              // 0..127
            int c4 = (idx & 7) * 4;        // 0..28
            float4 va = *(const float4*)(A + (size_t)(bm + r) * K + k0 + c4);
            split_store(sAh, sAl, r * LDSS + c4, va);
            float4 vb = *(const float4*)(B + (size_t)(bn + r) * K + k0 + c4);
            split_store(sBh, sBl, r * LDSS + c4, vb);
        }
        __syncthreads();

#pragma unroll
        for (int ks = 0; ks < 2; ks++) {
            uint32_t ah[4][4], al[4][4], bh[4][2], bl[4][2];
#pragma unroll
            for (int mt = 0; mt < 4; mt++) {
                int off = (arow + mt * 16) * LDSS + ks * 16 + akoff;
                uint32_t adH = smem_addr_u32(sAh + off);
                uint32_t adL = smem_addr_u32(sAl + off);
                LDSM4(ah[mt][0], ah[mt][1], ah[mt][2], ah[mt][3], adH);
                LDSM4(al[mt][0], al[mt][1], al[mt][2], al[mt][3], adL);
            }
#pragma unroll
            for (int np = 0; np < 2; np++) {
                int off = (brow + np * 16) * LDSS + ks * 16 + bkoff;
                uint32_t adH = smem_addr_u32(sBh + off);
                uint32_t adL = smem_addr_u32(sBl + off);
                LDSM4(bh[2 * np][0], bh[2 * np][1], bh[2 * np + 1][0], bh[2 * np + 1][1], adH);
                LDSM4(bl[2 * np][0], bl[2 * np][1], bl[2 * np + 1][0], bl[2 * np + 1][1], adL);
            }
#pragma unroll
            for (int mt = 0; mt < 4; mt++) {
#pragma unroll
                for (int nt = 0; nt < 4; nt++) {
                    MMA16816(acc[mt][nt], ah[mt][0], ah[mt][1], ah[mt][2], ah[mt][3],
                             bh[nt][0], bh[nt][1]);
                    MMA16816(acc[mt][nt], ah[mt][0], ah[mt][1], ah[mt][2], ah[mt][3],
                             bl[nt][0], bl[nt][1]);
                    MMA16816(acc[mt][nt], al[mt][0], al[mt][1], al[mt][2], al[mt][3],
                             bh[nt][0], bh[nt][1]);
                }
            }
        }
    }

    // Epilogue: direct float2 stores
#pragma unroll
    for (int mt = 0; mt < 4; mt++) {
#pragma unroll
        for (int nt = 0; nt < 4; nt++) {
            float* p = C + (size_t)(bm + wm + mt * 16 + g) * N + bn + wn + nt * 8 + tig * 2;
            *(float2*)p = make_float2(acc[mt][nt][0], acc[mt][nt][1]);
            *(float2*)(p + (size_t)8 * N) = make_float2(acc[mt][nt][2], acc[mt][nt][3]);
        }
    }
}

// ---------------------------------------------------------------------------
// RoPE tables (fp64 for accuracy vs fp32 JAX reference)
// ---------------------------------------------------------------------------
__global__ void rope_tables_kernel(float* ct, float* st) {
    int t = blockIdx.x;
    int l = threadIdx.x;     // 0..31
    double c = 1.0, s = 0.0;
    if (l < 16) {
        double freq = exp(-((double)l / 15.0) * log(1024.0));
        double th = (double)t * freq;
        c = cos(th);
        s = sin(th);
    }
    ct[t * 32 + l] = (float)c;
    st[t * 32 + l] = (float)s;
}

// ---------------------------------------------------------------------------
// Post-QKV: RMSNorm(q,k) -> RoPE(q,k), v *= lambdas[0]. One warp per (t,h).
// ---------------------------------------------------------------------------
__global__ void __launch_bounds__(256) qkv_post_kernel(const float* __restrict__ lambdas) {
    int w = (blockIdx.x * blockDim.x + threadIdx.x) >> 5;   // 0 .. T*H-1
    int lane = threadIdx.x & 31;
    int t = w >> 4;
    int h = w & 15;

    const float* base = g_qkv + (size_t)t * HD3 + h * HDIM;
    float c = g_cos[t * 32 + lane];
    float s = g_sin[t * 32 + lane];

    // ---- Q ----
    {
        float x1 = base[lane];
        float x2 = base[32 + lane];
        float ss = x1 * x1 + x2 * x2;
#pragma unroll
        for (int off = 16; off; off >>= 1) ss += __shfl_xor_sync(0xffffffffu, ss, off);
        float rn = 1.0f / sqrtf(ss * (1.0f / 64.0f) + RMS_EPS);
        x1 *= rn; x2 *= rn;
        float y1 = x1 * c + x2 * s;
        float y2 = x2 * c - x1 * s;
        float* out = g_Q + ((size_t)h * T_SEQ + t) * HDIM;
        out[lane] = y1;
        out[32 + lane] = y2;
    }
    // ---- K ----
    {
        float x1 = base[1024 + lane];
        float x2 = base[1024 + 32 + lane];
        float ss = x1 * x1 + x2 * x2;
#pragma unroll
        for (int off = 16; off; off >>= 1) ss += __shfl_xor_sync(0xffffffffu, ss, off);
        float rn = 1.0f / sqrtf(ss * (1.0f / 64.0f) + RMS_EPS);
        x1 *= rn; x2 *= rn;
        float y1 = x1 * c + x2 * s;
        float y2 = x2 * c - x1 * s;
        float* out = g_K + ((size_t)h * T_SEQ + t) * HDIM;
        out[lane] = y1;
        out[32 + lane] = y2;
    }
    // ---- V ----
    {
        float lam = lambdas[0];
        float* out = g_V + ((size_t)h * T_SEQ + t) * HDIM;
        out[lane] = lam * base[2048 + lane];
        out[32 + lane] = lam * base[2048 + 32 + lane];
    }
}

// ---------------------------------------------------------------------------
// Causal flash attention, fp32. 64x64 tiles. (unchanged, passing at R2)
// ---------------------------------------------------------------------------
__device__ __forceinline__ int kswz(int d, int c) {
    return d * 64 + ((c + d * 8) & 63);
}

__global__ void __launch_bounds__(256) flash_attn_kernel() {
    __shared__ float Qs[64 * 64];    // [r][d] row-major
    __shared__ float Kst[64 * 64];   // swizzled [d][c]
    __shared__ float Vs[64 * 64];    // [c][d] row-major

    int qt = blockIdx.x;        // q tile, 0..63
    int h = blockIdx.y;
    int tid = threadIdx.x;
    int lane = tid & 31;
    int l8 = tid & 7;
    int rw = tid >> 3;          // 0..31
    const float scale = 0.125f;
    const float NEG_INF = -__int_as_float(0x7f800000);

    const float* Qh = g_Q + ((size_t)h * T_SEQ + qt * 64) * HDIM;
    const float* Kh = g_K + (size_t)h * T_SEQ * HDIM;
    const float* Vh = g_V + (size_t)h * T_SEQ * HDIM;

#pragma unroll
    for (int i = 0; i < 16; i++) {
        int idx = tid + 256 * i;
        int rr = idx >> 6, d = idx & 63;
        Qs[rr * 64 + d] = Qh[rr * 64 + d];
    }

    float o0[8], o1[8];
#pragma unroll
    for (int j = 0; j < 8; j++) { o0[j] = 0.0f; o1[j] = 0.0f; }
    float m0 = NEG_INF, m1 = NEG_INF, l0 = 0.0f, l1 = 0.0f;

    for (int kt = 0; kt <= qt; kt++) {
        __syncthreads();
#pragma unroll
        for (int i = 0; i < 16; i++) {
            int idx = tid + 256 * i;
            int cc = idx >> 6, d = idx & 63;
            Kst[kswz(d, cc)] = Kh[(size_t)(kt * 64 + cc) * 64 + d];
            Vs[cc * 64 + d] = Vh[(size_t)(kt * 64 + cc) * 64 + d];
        }
        __syncthreads();

        float s0[8], s1[8];
#pragma unroll
        for (int j = 0; j < 8; j++) { s0[j] = 0.0f; s1[j] = 0.0f; }

#pragma unroll 16
        for (int d = 0; d < 64; d++) {
            float q0 = Qs[rw * 64 + d];
            float q1 = Qs[(rw + 32) * 64 + d];
#pragma unroll
            for (int jj = 0; jj < 8; jj++) {
                float kv = Kst[kswz(d, jj * 8 + l8)];
                s0[jj] += q0 * kv;
                s1[jj] += q1 * kv;
            }
        }

        bool diag = (kt == qt);
        float tm0 = NEG_INF, tm1 = NEG_INF;
#pragma unroll
        for (int jj = 0; jj < 8; jj++) {
            int c = jj * 8 + l8;
            float v0 = s0[jj] * scale;
            float v1 = s1[jj] * scale;
            if (diag) {
                if (c > rw) v0 = NEG_INF;
                if (c > rw + 32) v1 = NEG_INF;
            }
            s0[jj] = v0; s1[jj] = v1;
            tm0 = fmaxf(tm0, v0);
            tm1 = fmaxf(tm1, v1);
        }
#pragma unroll
        for (int off = 1; off < 8; off <<= 1) {
            tm0 = fmaxf(tm0, __shfl_xor_sync(0xffffffffu, tm0, off));
            tm1 = fmaxf(tm1, __shfl_xor_sync(0xffffffffu, tm1, off));
        }
        float nm0 = fmaxf(m0, tm0);
        float nm1 = fmaxf(m1, tm1);
        float cor0 = expf(m0 - nm0);
        float cor1 = expf(m1 - nm1);

        float ps0 = 0.0f, ps1 = 0.0f;
#pragma unroll
        for (int jj = 0; jj < 8; jj++) {
            float p0 = expf(s0[jj] - nm0);
            float p1 = expf(s1[jj] - nm1);
            s0[jj] = p0; s1[jj] = p1;
            ps0 += p0; ps1 += p1;
        }
#pragma unroll
        for (int off = 1; off < 8; off <<= 1) {
            ps0 += __shfl_xor_sync(0xffffffffu, ps0, off);
            ps1 += __shfl_xor_sync(0xffffffffu, ps1, off);
        }
        l0 = l0 * cor0 + ps0;
        l1 = l1 * cor1 + ps1;
#pragma unroll
        for (int jj = 0; jj < 8; jj++) { o0[jj] *= cor0; o1[jj] *= cor1; }
        m0 = nm0; m1 = nm1;

        int lbase = lane & ~7;
#pragma unroll
        for (int c = 0; c < 64; c++) {
            float p0 = __shfl_sync(0xffffffffu, s0[c >> 3], lbase + (c & 7));
            float p1 = __shfl_sync(0xffffffffu, s1[c >> 3], lbase + (c & 7));
#pragma unroll
            for (int jj = 0; jj < 8; jj++) {
                float vv = Vs[c * 64 + jj * 8 + l8];
                o0[jj] += p0 * vv;
                o1[jj] += p1 * vv;
            }
        }
    }

    float inv0 = 1.0f / l0;
    float inv1 = 1.0f / l1;
    int t0 = qt * 64 + rw;
    int t1 = t0 + 32;
#pragma unroll
    for (int jj = 0; jj < 8; jj++) {
        g_Y[(size_t)t0 * DIM + h * HDIM + jj * 8 + l8] = o0[jj] * inv0;
        g_Y[(size_t)t1 * DIM + h * HDIM + jj * 8 + l8] = o1[jj] * inv1;
    }
}

// ---------------------------------------------------------------------------
// Launch
// ---------------------------------------------------------------------------
extern "C" void kernel_launch(void* const* d_in, const int* in_sizes, int n_in,
                              void* d_out, int out_size)
{
    const float* x = (const float*)d_in[0];        // [1,4096,1024]
    const float* qkv_w = (const float*)d_in[1];    // [3072,1024]
    const float* lambdas = (const float*)d_in[2];  // [1]
    const float* proj_w = (const float*)d_in[3];   // [1024,1024]
    float* out = (float*)d_out;

    float *p_qkv, *p_Y, *p_cos, *p_sin;
    cudaGetSymbolAddress((void**)&p_qkv, g_qkv);
    cudaGetSymbolAddress((void**)&p_Y, g_Y);
    cudaGetSymbolAddress((void**)&p_cos, g_cos);
    cudaGetSymbolAddress((void**)&p_sin, g_sin);

    // 0) RoPE tables
    rope_tables_kernel<<<T_SEQ, 32>>>(p_cos, p_sin);

    // 1) QKV GEMM (mma.sync bf16-split): [4096,1024] x [3072,1024]^T
    {
        dim3 grid(HD3 / 128, T_SEQ / 128);
        gemm_mma_kernel<<<grid, 256>>>(x, qkv_w, p_qkv, HD3, DIM);
    }

    // 2) RMSNorm + RoPE + lambda*v
    {
        int warps = T_SEQ * NHEAD;
        qkv_post_kernel<<<warps * 32 / 256, 256>>>(lambdas);
    }

    // 3) Causal flash attention
    {
        dim3 grid(T_SEQ / 64, NHEAD);
        flash_attn_kernel<<<grid, 256>>>();
    }

    // 4) Proj GEMM (mma.sync bf16-split): [4096,1024] x [1024,1024]^T
    {
        dim3 grid(DIM / 128, T_SEQ / 128);
        gemm_mma_kernel<<<grid, 256>>>(p_Y, proj_w, out, DIM, DIM);
    }
}

// round 5
// speedup vs baseline: 2.8822x; 2.3949x over previous
#include <cuda_runtime.h>
#include <cuda_bf16.h>
#include <math.h>
#include <stdint.h>

// Problem constants
#define T_SEQ 4096
#define DIM 1024
#define NHEAD 16
#define HDIM 64
#define HD3 3072          // 3*NHEAD*HDIM
#define RMS_EPS 1e-6f

// ---------------------------------------------------------------------------
// Scratch (device globals; no allocation allowed)
// ---------------------------------------------------------------------------
__device__ float g_qkv[T_SEQ * HD3];              // [t][f]
__device__ float g_Y[T_SEQ * DIM];                // attention out, [t][h*64+d]
__device__ float g_cos[T_SEQ * 32];
__device__ float g_sin[T_SEQ * 32];
// bf16 hi/lo splits for attention operands
__device__ __nv_bfloat16 g_Qh[NHEAD * T_SEQ * HDIM];   // [h][t][d]
__device__ __nv_bfloat16 g_Ql[NHEAD * T_SEQ * HDIM];
__device__ __nv_bfloat16 g_Kh[NHEAD * T_SEQ * HDIM];   // [h][t][d]
__device__ __nv_bfloat16 g_Kl[NHEAD * T_SEQ * HDIM];
__device__ __nv_bfloat16 g_Vth[NHEAD * HDIM * T_SEQ];  // [h][d][t]  (lambda*v)
__device__ __nv_bfloat16 g_Vtl[NHEAD * HDIM * T_SEQ];

// ===========================================================================
// mma.sync helpers (baseline PTX, works on sm_100 without 'a' suffix)
// ===========================================================================
#define LDSM4(R0, R1, R2, R3, ADDR) \
    asm volatile("ldmatrix.sync.aligned.m8n8.x4.shared.b16 {%0,%1,%2,%3}, [%4];" \
        : "=r"(R0), "=r"(R1), "=r"(R2), "=r"(R3) : "r"(ADDR))

#define MMA16816(D, A0, A1, A2, A3, B0, B1) \
    asm volatile("mma.sync.aligned.m16n8k16.row.col.f32.bf16.bf16.f32 " \
        "{%0,%1,%2,%3}, {%4,%5,%6,%7}, {%8,%9}, {%0,%1,%2,%3};" \
        : "+f"((D)[0]), "+f"((D)[1]), "+f"((D)[2]), "+f"((D)[3]) \
        : "r"(A0), "r"(A1), "r"(A2), "r"(A3), "r"(B0), "r"(B1))

__device__ __forceinline__ uint32_t smem_addr_u32(const void* p) {
    return (uint32_t)__cvta_generic_to_shared(p);
}

__device__ __forceinline__ uint32_t pack_bf2(__nv_bfloat16 a, __nv_bfloat16 b) {
    union { __nv_bfloat162 v; uint32_t u; } t;
    t.v = __nv_bfloat162(a, b);   // .x = low 16 bits
    return t.u;
}

__device__ __forceinline__ void split_bf(float x, __nv_bfloat16& hi, __nv_bfloat16& lo) {
    hi = __float2bfloat16_rn(x);
    lo = __float2bfloat16_rn(x - __bfloat162float(hi));
}

// Split a float4 into hi/lo bf16 and store 4 halves to each of two smem tiles.
__device__ __forceinline__ void split_store(__nv_bfloat16* hi_t, __nv_bfloat16* lo_t,
                                            int off_halves, float4 v) {
    __nv_bfloat16 h0, h1, h2, h3, l0, l1, l2, l3;
    split_bf(v.x, h0, l0); split_bf(v.y, h1, l1);
    split_bf(v.z, h2, l2); split_bf(v.w, h3, l3);
    *(uint2*)((char*)hi_t + off_halves * 2) = make_uint2(pack_bf2(h0, h1), pack_bf2(h2, h3));
    *(uint2*)((char*)lo_t + off_halves * 2) = make_uint2(pack_bf2(l0, l1), pack_bf2(l2, l3));
}

// ===========================================================================
// bf16-split TN GEMM via mma.sync (unchanged from R4, proven)
// ===========================================================================
#define LDSS 40   // smem row stride in halves

__global__ void __launch_bounds__(256, 1) gemm_mma_kernel(
    const float* __restrict__ A, const float* __restrict__ B,
    float* __restrict__ C, int N, int K)
{
    __shared__ __align__(16) __nv_bfloat16 sAh[128 * LDSS];
    __shared__ __align__(16) __nv_bfloat16 sAl[128 * LDSS];
    __shared__ __align__(16) __nv_bfloat16 sBh[128 * LDSS];
    __shared__ __align__(16) __nv_bfloat16 sBl[128 * LDSS];

    int tid = threadIdx.x;
    int wid = tid >> 5;
    int lane = tid & 31;
    int bm = blockIdx.y * 128;
    int bn = blockIdx.x * 128;
    int wm = (wid & 1) * 64;
    int wn = (wid >> 1) * 32;
    int g = lane >> 2;
    int tig = lane & 3;

    float acc[4][4][4];
#pragma unroll
    for (int mt = 0; mt < 4; mt++)
#pragma unroll
        for (int nt = 0; nt < 4; nt++)
#pragma unroll
            for (int r = 0; r < 4; r++) acc[mt][nt][r] = 0.0f;

    int arow = wm + (lane & 15);
    int akoff = (lane >> 4) * 8;
    int brow = wn + (lane & 7) + ((lane >> 4) & 1) * 8;
    int bkoff = ((lane >> 3) & 1) * 8;

    const int NCHUNK = K / 32;
    for (int ch = 0; ch < NCHUNK; ch++) {
        int k0 = ch * 32;
        __syncthreads();
#pragma unroll
        for (int i = 0; i < 4; i++) {
            int idx = tid + 256 * i;
            int r = idx >> 3;
            int c4 = (idx & 7) * 4;
            float4 va = *(const float4*)(A + (size_t)(bm + r) * K + k0 + c4);
            split_store(sAh, sAl, r * LDSS + c4, va);
            float4 vb = *(const float4*)(B + (size_t)(bn + r) * K + k0 + c4);
            split_store(sBh, sBl, r * LDSS + c4, vb);
        }
        __syncthreads();

#pragma unroll
        for (int ks = 0; ks < 2; ks++) {
            uint32_t ah[4][4], al[4][4], bh[4][2], bl[4][2];
#pragma unroll
            for (int mt = 0; mt < 4; mt++) {
                int off = (arow + mt * 16) * LDSS + ks * 16 + akoff;
                LDSM4(ah[mt][0], ah[mt][1], ah[mt][2], ah[mt][3], smem_addr_u32(sAh + off));
                LDSM4(al[mt][0], al[mt][1], al[mt][2], al[mt][3], smem_addr_u32(sAl + off));
            }
#pragma unroll
            for (int np = 0; np < 2; np++) {
                int off = (brow + np * 16) * LDSS + ks * 16 + bkoff;
                LDSM4(bh[2 * np][0], bh[2 * np][1], bh[2 * np + 1][0], bh[2 * np + 1][1],
                      smem_addr_u32(sBh + off));
                LDSM4(bl[2 * np][0], bl[2 * np][1], bl[2 * np + 1][0], bl[2 * np + 1][1],
                      smem_addr_u32(sBl + off));
            }
#pragma unroll
            for (int mt = 0; mt < 4; mt++) {
#pragma unroll
                for (int nt = 0; nt < 4; nt++) {
                    MMA16816(acc[mt][nt], ah[mt][0], ah[mt][1], ah[mt][2], ah[mt][3],
                             bh[nt][0], bh[nt][1]);
                    MMA16816(acc[mt][nt], ah[mt][0], ah[mt][1], ah[mt][2], ah[mt][3],
                             bl[nt][0], bl[nt][1]);
                    MMA16816(acc[mt][nt], al[mt][0], al[mt][1], al[mt][2], al[mt][3],
                             bh[nt][0], bh[nt][1]);
                }
            }
        }
    }

#pragma unroll
    for (int mt = 0; mt < 4; mt++) {
#pragma unroll
        for (int nt = 0; nt < 4; nt++) {
            float* p = C + (size_t)(bm + wm + mt * 16 + g) * N + bn + wn + nt * 8 + tig * 2;
            *(float2*)p = make_float2(acc[mt][nt][0], acc[mt][nt][1]);
            *(float2*)(p + (size_t)8 * N) = make_float2(acc[mt][nt][2], acc[mt][nt][3]);
        }
    }
}

// ---------------------------------------------------------------------------
// RoPE tables (fp64 for accuracy vs fp32 JAX reference)
// ---------------------------------------------------------------------------
__global__ void rope_tables_kernel(float* ct, float* st) {
    int t = blockIdx.x;
    int l = threadIdx.x;     // 0..31
    double c = 1.0, s = 0.0;
    if (l < 16) {
        double freq = exp(-((double)l / 15.0) * log(1024.0));
        double th = (double)t * freq;
        c = cos(th);
        s = sin(th);
    }
    ct[t * 32 + l] = (float)c;
    st[t * 32 + l] = (float)s;
}

// ---------------------------------------------------------------------------
// Post-QKV: RMSNorm(q,k) -> RoPE(q,k), v *= lambdas[0].
// Emits bf16 hi/lo splits: Q,K as [h][t][d]; V transposed [h][d][t].
// One warp per (t, head).
// ---------------------------------------------------------------------------
__global__ void __launch_bounds__(256) qkv_post_kernel(const float* __restrict__ lambdas) {
    int w = (blockIdx.x * blockDim.x + threadIdx.x) >> 5;   // 0 .. T*H-1
    int lane = threadIdx.x & 31;
    int t = w >> 4;
    int hd = w & 15;

    const float* base = g_qkv + (size_t)t * HD3 + hd * HDIM;
    float c = g_cos[t * 32 + lane];
    float s = g_sin[t * 32 + lane];

    size_t qk_off = ((size_t)hd * T_SEQ + t) * HDIM;
    __nv_bfloat16 hi, lo;

    // ---- Q ----
    {
        float x1 = base[lane];
        float x2 = base[32 + lane];
        float ss = x1 * x1 + x2 * x2;
#pragma unroll
        for (int off = 16; off; off >>= 1) ss += __shfl_xor_sync(0xffffffffu, ss, off);
        float rn = 1.0f / sqrtf(ss * (1.0f / 64.0f) + RMS_EPS);
        x1 *= rn; x2 *= rn;
        float y1 = x1 * c + x2 * s;
        float y2 = x2 * c - x1 * s;
        split_bf(y1, hi, lo);
        g_Qh[qk_off + lane] = hi; g_Ql[qk_off + lane] = lo;
        split_bf(y2, hi, lo);
        g_Qh[qk_off + 32 + lane] = hi; g_Ql[qk_off + 32 + lane] = lo;
    }
    // ---- K ----
    {
        float x1 = base[1024 + lane];
        float x2 = base[1024 + 32 + lane];
        float ss = x1 * x1 + x2 * x2;
#pragma unroll
        for (int off = 16; off; off >>= 1) ss += __shfl_xor_sync(0xffffffffu, ss, off);
        float rn = 1.0f / sqrtf(ss * (1.0f / 64.0f) + RMS_EPS);
        x1 *= rn; x2 *= rn;
        float y1 = x1 * c + x2 * s;
        float y2 = x2 * c - x1 * s;
        split_bf(y1, hi, lo);
        g_Kh[qk_off + lane] = hi; g_Kl[qk_off + lane] = lo;
        split_bf(y2, hi, lo);
        g_Kh[qk_off + 32 + lane] = hi; g_Kl[qk_off + 32 + lane] = lo;
    }
    // ---- V (transposed [h][d][t]) ----
    {
        float lam = lambdas[0];
        float v1 = lam * base[2048 + lane];
        float v2 = lam * base[2048 + 32 + lane];
        size_t vo1 = ((size_t)hd * HDIM + lane) * T_SEQ + t;
        size_t vo2 = ((size_t)hd * HDIM + 32 + lane) * T_SEQ + t;
        split_bf(v1, hi, lo);
        g_Vth[vo1] = hi; g_Vtl[vo1] = lo;
        split_bf(v2, hi, lo);
        g_Vth[vo2] = hi; g_Vtl[vo2] = lo;
    }
}

// ===========================================================================
// Causal flash attention on tensor cores (mma.sync bf16-split).
// CTA: 128 q rows x 64 kv step; 8 warps, m16 per warp; D=64.
// ===========================================================================
#define FLS 72    // smem row stride in halves (144B -> conflict-free ldmatrix)

__global__ void __launch_bounds__(256, 1) flash_mma_kernel() {
    __shared__ __align__(16) __nv_bfloat16 sK[2][64 * FLS];   // K hi/lo [kv][d]
    __shared__ __align__(16) __nv_bfloat16 sV[2][64 * FLS];   // Vt hi/lo [d][kv]

    int qb = blockIdx.x;       // 0..31
    int hd = blockIdx.y;       // head
    int tid = threadIdx.x;
    int wid = tid >> 5;
    int lane = tid & 31;
    int g = lane >> 2;
    int tig = lane & 3;
    int qbase = qb * 128;
    int r0 = qbase + wid * 16 + g;       // absolute q row (fragment row g)
    int r1 = r0 + 8;                     // fragment row g+8
    const float SCL = 0.125f * 1.44269504088896340736f;   // 1/8 * log2(e)

    const __nv_bfloat16* Qh_g = g_Qh + ((size_t)hd * T_SEQ + qbase) * HDIM;
    const __nv_bfloat16* Ql_g = g_Ql + ((size_t)hd * T_SEQ + qbase) * HDIM;
    const __nv_bfloat16* Kh_g = g_Kh + (size_t)hd * T_SEQ * HDIM;
    const __nv_bfloat16* Kl_g = g_Kl + (size_t)hd * T_SEQ * HDIM;
    const __nv_bfloat16* Vth_g = g_Vth + (size_t)hd * HDIM * T_SEQ;
    const __nv_bfloat16* Vtl_g = g_Vtl + (size_t)hd * HDIM * T_SEQ;

    // ldmatrix addressing (identical scheme to the proven GEMM kernel)
    int a_off = (wid * 16 + (lane & 15)) * FLS + (lane >> 4) * 8;   // A frags (Q)
    int b_row = (lane & 7) + ((lane >> 4) & 1) * 8;                 // B frags
    int b_koff = ((lane >> 3) & 1) * 8;

    __nv_bfloat16* stage = &sK[0][0];    // 128*FLS halves spans sK[0..1]

    // ---- Stage Q and load fragments into registers ----
    uint32_t qh[4][4], ql[4][4];
#pragma unroll
    for (int i = 0; i < 4; i++) {
        int idx = tid + 256 * i;          // 0..1023
        int r = idx >> 3, c8 = (idx & 7) * 8;
        *(uint4*)&stage[r * FLS + c8] = *(const uint4*)(Qh_g + (size_t)r * HDIM + c8);
    }
    __syncthreads();
#pragma unroll
    for (int ks = 0; ks < 4; ks++)
        LDSM4(qh[ks][0], qh[ks][1], qh[ks][2], qh[ks][3],
              smem_addr_u32(stage + a_off + ks * 16));
    __syncthreads();
#pragma unroll
    for (int i = 0; i < 4; i++) {
        int idx = tid + 256 * i;
        int r = idx >> 3, c8 = (idx & 7) * 8;
        *(uint4*)&stage[r * FLS + c8] = *(const uint4*)(Ql_g + (size_t)r * HDIM + c8);
    }
    __syncthreads();
#pragma unroll
    for (int ks = 0; ks < 4; ks++)
        LDSM4(ql[ks][0], ql[ks][1], ql[ks][2], ql[ks][3],
              smem_addr_u32(stage + a_off + ks * 16));

    // ---- Online softmax state & output accumulators ----
    float m0 = -1e30f, m1 = -1e30f, l0 = 0.0f, l1 = 0.0f;
    float acc_o[8][4];
#pragma unroll
    for (int j = 0; j < 8; j++)
#pragma unroll
        for (int r = 0; r < 4; r++) acc_o[j][r] = 0.0f;

    int ntiles = 2 * qb + 2;
    for (int kt = 0; kt < ntiles; kt++) {
        int kv0 = kt * 64;
        __syncthreads();
#pragma unroll
        for (int i = 0; i < 2; i++) {
            int idx = tid + 256 * i;      // 0..511
            int r = idx >> 3, c8 = (idx & 7) * 8;
            *(uint4*)&sK[0][r * FLS + c8] = *(const uint4*)(Kh_g + (size_t)(kv0 + r) * HDIM + c8);
            *(uint4*)&sK[1][r * FLS + c8] = *(const uint4*)(Kl_g + (size_t)(kv0 + r) * HDIM + c8);
            *(uint4*)&sV[0][r * FLS + c8] = *(const uint4*)(Vth_g + (size_t)r * T_SEQ + kv0 + c8);
            *(uint4*)&sV[1][r * FLS + c8] = *(const uint4*)(Vtl_g + (size_t)r * T_SEQ + kv0 + c8);
        }
        __syncthreads();

        if (kv0 > qbase + wid * 16 + 15) continue;   // tile fully above diagonal

        // ---- S = Q K^T (split: 3 MMAs) ----
        float acc_s[8][4];
#pragma unroll
        for (int j = 0; j < 8; j++)
#pragma unroll
            for (int r = 0; r < 4; r++) acc_s[j][r] = 0.0f;

#pragma unroll
        for (int g2 = 0; g2 < 4; g2++) {
            int roff = (b_row + g2 * 16) * FLS + b_koff;
#pragma unroll
            for (int ks = 0; ks < 4; ks++) {
                uint32_t bh0, bh1, bh2, bh3, bl0, bl1, bl2, bl3;
                LDSM4(bh0, bh1, bh2, bh3, smem_addr_u32(&sK[0][0] + roff + ks * 16));
                LDSM4(bl0, bl1, bl2, bl3, smem_addr_u32(&sK[1][0] + roff + ks * 16));
                MMA16816(acc_s[2 * g2], qh[ks][0], qh[ks][1], qh[ks][2], qh[ks][3], bh0, bh1);
                MMA16816(acc_s[2 * g2], qh[ks][0], qh[ks][1], qh[ks][2], qh[ks][3], bl0, bl1);
                MMA16816(acc_s[2 * g2], ql[ks][0], ql[ks][1], ql[ks][2], ql[ks][3], bh0, bh1);
                MMA16816(acc_s[2 * g2 + 1], qh[ks][0], qh[ks][1], qh[ks][2], qh[ks][3], bh2, bh3);
                MMA16816(acc_s[2 * g2 + 1], qh[ks][0], qh[ks][1], qh[ks][2], qh[ks][3], bl2, bl3);
                MMA16816(acc_s[2 * g2 + 1], ql[ks][0], ql[ks][1], ql[ks][2], ql[ks][3], bh2, bh3);
            }
        }

        // ---- scale, causal mask, row max ----
        float tm0 = -1e30f, tm1 = -1e30f;
#pragma unroll
        for (int j = 0; j < 8; j++) {
            int cc = kv0 + 8 * j + 2 * tig;
            float s0 = acc_s[j][0] * SCL; if (cc > r0) s0 = -1e30f;
            float s1 = acc_s[j][1] * SCL; if (cc + 1 > r0) s1 = -1e30f;
            float s2 = acc_s[j][2] * SCL; if (cc > r1) s2 = -1e30f;
            float s3 = acc_s[j][3] * SCL; if (cc + 1 > r1) s3 = -1e30f;
            acc_s[j][0] = s0; acc_s[j][1] = s1; acc_s[j][2] = s2; acc_s[j][3] = s3;
            tm0 = fmaxf(tm0, fmaxf(s0, s1));
            tm1 = fmaxf(tm1, fmaxf(s2, s3));
        }
        tm0 = fmaxf(tm0, __shfl_xor_sync(0xffffffffu, tm0, 1));
        tm0 = fmaxf(tm0, __shfl_xor_sync(0xffffffffu, tm0, 2));
        tm1 = fmaxf(tm1, __shfl_xor_sync(0xffffffffu, tm1, 1));
        tm1 = fmaxf(tm1, __shfl_xor_sync(0xffffffffu, tm1, 2));

        float nm0 = fmaxf(m0, tm0);
        float nm1 = fmaxf(m1, tm1);
        float f0 = exp2f(m0 - nm0);
        float f1 = exp2f(m1 - nm1);

        float ps0 = 0.0f, ps1 = 0.0f;
#pragma unroll
        for (int j = 0; j < 8; j++) {
            float p0 = exp2f(acc_s[j][0] - nm0);
            float p1 = exp2f(acc_s[j][1] - nm0);
            float p2 = exp2f(acc_s[j][2] - nm1);
            float p3 = exp2f(acc_s[j][3] - nm1);
            acc_s[j][0] = p0; acc_s[j][1] = p1; acc_s[j][2] = p2; acc_s[j][3] = p3;
            ps0 += p0 + p1; ps1 += p2 + p3;
        }
        l0 = l0 * f0 + ps0;
        l1 = l1 * f1 + ps1;
#pragma unroll
        for (int j = 0; j < 8; j++) {
            acc_o[j][0] *= f0; acc_o[j][1] *= f0;
            acc_o[j][2] *= f1; acc_o[j][3] *= f1;
        }
        m0 = nm0; m1 = nm1;

        // ---- pack P hi/lo A-fragments from accumulators ----
        uint32_t ph[4][4], pl[4][4];
#pragma unroll
        for (int kc = 0; kc < 4; kc++) {
            __nv_bfloat16 ha, la, hb, lb;
            split_bf(acc_s[2 * kc][0], ha, la); split_bf(acc_s[2 * kc][1], hb, lb);
            ph[kc][0] = pack_bf2(ha, hb); pl[kc][0] = pack_bf2(la, lb);
            split_bf(acc_s[2 * kc][2], ha, la); split_bf(acc_s[2 * kc][3], hb, lb);
            ph[kc][1] = pack_bf2(ha, hb); pl[kc][1] = pack_bf2(la, lb);
            split_bf(acc_s[2 * kc + 1][0], ha, la); split_bf(acc_s[2 * kc + 1][1], hb, lb);
            ph[kc][2] = pack_bf2(ha, hb); pl[kc][2] = pack_bf2(la, lb);
            split_bf(acc_s[2 * kc + 1][2], ha, la); split_bf(acc_s[2 * kc + 1][3], hb, lb);
            ph[kc][3] = pack_bf2(ha, hb); pl[kc][3] = pack_bf2(la, lb);
        }

        // ---- O += P V (split: 3 MMAs) ----
#pragma unroll
        for (int g2 = 0; g2 < 4; g2++) {
            int roff = (b_row + g2 * 16) * FLS + b_koff;
#pragma unroll
            for (int kc = 0; kc < 4; kc++) {
                uint32_t vh0, vh1, vh2, vh3, vl0, vl1, vl2, vl3;
                LDSM4(vh0, vh1, vh2, vh3, smem_addr_u32(&sV[0][0] + roff + kc * 16));
                LDSM4(vl0, vl1, vl2, vl3, smem_addr_u32(&sV[1][0] + roff + kc * 16));
                MMA16816(acc_o[2 * g2], ph[kc][0], ph[kc][1], ph[kc][2], ph[kc][3], vh0, vh1);
                MMA16816(acc_o[2 * g2], pl[kc][0], pl[kc][1], pl[kc][2], pl[kc][3], vh0, vh1);
                MMA16816(acc_o[2 * g2], ph[kc][0], ph[kc][1], ph[kc][2], ph[kc][3], vl0, vl1);
                MMA16816(acc_o[2 * g2 + 1], ph[kc][0], ph[kc][1], ph[kc][2], ph[kc][3], vh2, vh3);
                MMA16816(acc_o[2 * g2 + 1], pl[kc][0], pl[kc][1], pl[kc][2], pl[kc][3], vh2, vh3);
                MMA16816(acc_o[2 * g2 + 1], ph[kc][0], ph[kc][1], ph[kc][2], ph[kc][3], vl2, vl3);
            }
        }
    }

    // ---- finalize: reduce l across quad, normalize, store ----
    l0 += __shfl_xor_sync(0xffffffffu, l0, 1);
    l0 += __shfl_xor_sync(0xffffffffu, l0, 2);
    l1 += __shfl_xor_sync(0xffffffffu, l1, 1);
    l1 += __shfl_xor_sync(0xffffffffu, l1, 2);
    float inv0 = 1.0f / l0;
    float inv1 = 1.0f / l1;

#pragma unroll
    for (int j = 0; j < 8; j++) {
        size_t base = (size_t)r0 * DIM + hd * HDIM + 8 * j + 2 * tig;
        *(float2*)&g_Y[base] = make_float2(acc_o[j][0] * inv0, acc_o[j][1] * inv0);
        *(float2*)&g_Y[base + (size_t)8 * DIM] = make_float2(acc_o[j][2] * inv1, acc_o[j][3] * inv1);
    }
}

// ---------------------------------------------------------------------------
// Launch
// ---------------------------------------------------------------------------
extern "C" void kernel_launch(void* const* d_in, const int* in_sizes, int n_in,
                              void* d_out, int out_size)
{
    const float* x = (const float*)d_in[0];        // [1,4096,1024]
    const float* qkv_w = (const float*)d_in[1];    // [3072,1024]
    const float* lambdas = (const float*)d_in[2];  // [1]
    const float* proj_w = (const float*)d_in[3];   // [1024,1024]
    float* out = (float*)d_out;

    float *p_qkv, *p_Y, *p_cos, *p_sin;
    cudaGetSymbolAddress((void**)&p_qkv, g_qkv);
    cudaGetSymbolAddress((void**)&p_Y, g_Y);
    cudaGetSymbolAddress((void**)&p_cos, g_cos);
    cudaGetSymbolAddress((void**)&p_sin, g_sin);

    // 0) RoPE tables
    rope_tables_kernel<<<T_SEQ, 32>>>(p_cos, p_sin);

    // 1) QKV GEMM (mma.sync bf16-split): [4096,1024] x [3072,1024]^T
    {
        dim3 grid(HD3 / 128, T_SEQ / 128);
        gemm_mma_kernel<<<grid, 256>>>(x, qkv_w, p_qkv, HD3, DIM);
    }

    // 2) RMSNorm + RoPE + lambda*v, emit bf16 hi/lo splits
    {
        int warps = T_SEQ * NHEAD;
        qkv_post_kernel<<<warps * 32 / 256, 256>>>(lambdas);
    }

    // 3) Causal flash attention (tensor cores)
    {
        dim3 grid(T_SEQ / 128, NHEAD);
        flash_mma_kernel<<<grid, 256>>>();
    }

    // 4) Proj GEMM (mma.sync bf16-split): [4096,1024] x [1024,1024]^T
    {
        dim3 grid(DIM / 128, T_SEQ / 128);
        gemm_mma_kernel<<<grid, 256>>>(p_Y, proj_w, out, DIM, DIM);
    }
}

// round 6
// speedup vs baseline: 2.8827x; 1.0002x over previous
#include <cuda_runtime.h>
#include <cuda_bf16.h>
#include <math.h>
#include <stdint.h>

// Problem constants
#define T_SEQ 4096
#define DIM 1024
#define NHEAD 16
#define HDIM 64
#define HD3 3072          // 3*NHEAD*HDIM
#define RMS_EPS 1e-6f

// ---------------------------------------------------------------------------
// Scratch (device globals; no allocation allowed)
// ---------------------------------------------------------------------------
__device__ float g_qkv[T_SEQ * HD3];              // [t][f]
__device__ float g_Y[T_SEQ * DIM];                // attention out, [t][h*64+d]
__device__ float g_cos[T_SEQ * 32];
__device__ float g_sin[T_SEQ * 32];
// bf16 hi/lo splits for attention operands
__device__ __nv_bfloat16 g_Qh[NHEAD * T_SEQ * HDIM];   // [h][t][d]
__device__ __nv_bfloat16 g_Ql[NHEAD * T_SEQ * HDIM];
__device__ __nv_bfloat16 g_Kh[NHEAD * T_SEQ * HDIM];   // [h][t][d]
__device__ __nv_bfloat16 g_Kl[NHEAD * T_SEQ * HDIM];
__device__ __nv_bfloat16 g_Vth[NHEAD * HDIM * T_SEQ];  // [h][d][t]  (lambda*v)
__device__ __nv_bfloat16 g_Vtl[NHEAD * HDIM * T_SEQ];

// ===========================================================================
// mma.sync helpers (baseline PTX, works on sm_100 without 'a' suffix)
// ===========================================================================
#define LDSM4(R0, R1, R2, R3, ADDR) \
    asm volatile("ldmatrix.sync.aligned.m8n8.x4.shared.b16 {%0,%1,%2,%3}, [%4];" \
        : "=r"(R0), "=r"(R1), "=r"(R2), "=r"(R3) : "r"(ADDR))

#define MMA16816(D, A0, A1, A2, A3, B0, B1) \
    asm volatile("mma.sync.aligned.m16n8k16.row.col.f32.bf16.bf16.f32 " \
        "{%0,%1,%2,%3}, {%4,%5,%6,%7}, {%8,%9}, {%0,%1,%2,%3};" \
        : "+f"((D)[0]), "+f"((D)[1]), "+f"((D)[2]), "+f"((D)[3]) \
        : "r"(A0), "r"(A1), "r"(A2), "r"(A3), "r"(B0), "r"(B1))

__device__ __forceinline__ uint32_t smem_addr_u32(const void* p) {
    return (uint32_t)__cvta_generic_to_shared(p);
}

__device__ __forceinline__ uint32_t pack_bf2(__nv_bfloat16 a, __nv_bfloat16 b) {
    union { __nv_bfloat162 v; uint32_t u; } t;
    t.v = __nv_bfloat162(a, b);   // .x = low 16 bits
    return t.u;
}

__device__ __forceinline__ void split_bf(float x, __nv_bfloat16& hi, __nv_bfloat16& lo) {
    hi = __float2bfloat16_rn(x);
    lo = __float2bfloat16_rn(x - __bfloat162float(hi));
}

// Split a float4 into hi/lo bf16 and store 4 halves to each of two smem tiles.
__device__ __forceinline__ void split_store(__nv_bfloat16* hi_t, __nv_bfloat16* lo_t,
                                            int off_halves, float4 v) {
    __nv_bfloat16 h0, h1, h2, h3, l0, l1, l2, l3;
    split_bf(v.x, h0, l0); split_bf(v.y, h1, l1);
    split_bf(v.z, h2, l2); split_bf(v.w, h3, l3);
    *(uint2*)((char*)hi_t + off_halves * 2) = make_uint2(pack_bf2(h0, h1), pack_bf2(h2, h3));
    *(uint2*)((char*)lo_t + off_halves * 2) = make_uint2(pack_bf2(l0, l1), pack_bf2(l2, l3));
}

// ===========================================================================
// bf16-split TN GEMM via mma.sync (unchanged from R4, proven)
// ===========================================================================
#define LDSS 40   // smem row stride in halves

__global__ void __launch_bounds__(256, 1) gemm_mma_kernel(
    const float* __restrict__ A, const float* __restrict__ B,
    float* __restrict__ C, int N, int K)
{
    __shared__ __align__(16) __nv_bfloat16 sAh[128 * LDSS];
    __shared__ __align__(16) __nv_bfloat16 sAl[128 * LDSS];
    __shared__ __align__(16) __nv_bfloat16 sBh[128 * LDSS];
    __shared__ __align__(16) __nv_bfloat16 sBl[128 * LDSS];

    int tid = threadIdx.x;
    int wid = tid >> 5;
    int lane = tid & 31;
    int bm = blockIdx.y * 128;
    int bn = blockIdx.x * 128;
    int wm = (wid & 1) * 64;
    int wn = (wid >> 1) * 32;
    int g = lane >> 2;
    int tig = lane & 3;

    float acc[4][4][4];
#pragma unroll
    for (int mt = 0; mt < 4; mt++)
#pragma unroll
        for (int nt = 0; nt < 4; nt++)
#pragma unroll
            for (int r = 0; r < 4; r++) acc[mt][nt][r] = 0.0f;

    int arow = wm + (lane & 15);
    int akoff = (lane >> 4) * 8;
    int brow = wn + (lane & 7) + ((lane >> 4) & 1) * 8;
    int bkoff = ((lane >> 3) & 1) * 8;

    const int NCHUNK = K / 32;
    for (int ch = 0; ch < NCHUNK; ch++) {
        int k0 = ch * 32;
        __syncthreads();
#pragma unroll
        for (int i = 0; i < 4; i++) {
            int idx = tid + 256 * i;
            int r = idx >> 3;
            int c4 = (idx & 7) * 4;
            float4 va = *(const float4*)(A + (size_t)(bm + r) * K + k0 + c4);
            split_store(sAh, sAl, r * LDSS + c4, va);
            float4 vb = *(const float4*)(B + (size_t)(bn + r) * K + k0 + c4);
            split_store(sBh, sBl, r * LDSS + c4, vb);
        }
        __syncthreads();

#pragma unroll
        for (int ks = 0; ks < 2; ks++) {
            uint32_t ah[4][4], al[4][4], bh[4][2], bl[4][2];
#pragma unroll
            for (int mt = 0; mt < 4; mt++) {
                int off = (arow + mt * 16) * LDSS + ks * 16 + akoff;
                LDSM4(ah[mt][0], ah[mt][1], ah[mt][2], ah[mt][3], smem_addr_u32(sAh + off));
                LDSM4(al[mt][0], al[mt][1], al[mt][2], al[mt][3], smem_addr_u32(sAl + off));
            }
#pragma unroll
            for (int np = 0; np < 2; np++) {
                int off = (brow + np * 16) * LDSS + ks * 16 + bkoff;
                LDSM4(bh[2 * np][0], bh[2 * np][1], bh[2 * np + 1][0], bh[2 * np + 1][1],
                      smem_addr_u32(sBh + off));
                LDSM4(bl[2 * np][0], bl[2 * np][1], bl[2 * np + 1][0], bl[2 * np + 1][1],
                      smem_addr_u32(sBl + off));
            }
#pragma unroll
            for (int mt = 0; mt < 4; mt++) {
#pragma unroll
                for (int nt = 0; nt < 4; nt++) {
                    MMA16816(acc[mt][nt], ah[mt][0], ah[mt][1], ah[mt][2], ah[mt][3],
                             bh[nt][0], bh[nt][1]);
                    MMA16816(acc[mt][nt], ah[mt][0], ah[mt][1], ah[mt][2], ah[mt][3],
                             bl[nt][0], bl[nt][1]);
                    MMA16816(acc[mt][nt], al[mt][0], al[mt][1], al[mt][2], al[mt][3],
                             bh[nt][0], bh[nt][1]);
                }
            }
        }
    }

#pragma unroll
    for (int mt = 0; mt < 4; mt++) {
#pragma unroll
        for (int nt = 0; nt < 4; nt++) {
            float* p = C + (size_t)(bm + wm + mt * 16 + g) * N + bn + wn + nt * 8 + tig * 2;
            *(float2*)p = make_float2(acc[mt][nt][0], acc[mt][nt][1]);
            *(float2*)(p + (size_t)8 * N) = make_float2(acc[mt][nt][2], acc[mt][nt][3]);
        }
    }
}

// ---------------------------------------------------------------------------
// RoPE tables (fp64 for accuracy vs fp32 JAX reference)
// ---------------------------------------------------------------------------
__global__ void rope_tables_kernel(float* ct, float* st) {
    int t = blockIdx.x;
    int l = threadIdx.x;     // 0..31
    double c = 1.0, s = 0.0;
    if (l < 16) {
        double freq = exp(-((double)l / 15.0) * log(1024.0));
        double th = (double)t * freq;
        c = cos(th);
        s = sin(th);
    }
    ct[t * 32 + l] = (float)c;
    st[t * 32 + l] = (float)s;
}

// ---------------------------------------------------------------------------
// Post-QKV: RMSNorm(q,k) -> RoPE(q,k), v *= lambdas[0].
// Emits bf16 hi/lo splits: Q,K as [h][t][d]; V transposed [h][d][t].
// One warp per (t, head).
// ---------------------------------------------------------------------------
__global__ void __launch_bounds__(256) qkv_post_kernel(const float* __restrict__ lambdas) {
    int w = (blockIdx.x * blockDim.x + threadIdx.x) >> 5;   // 0 .. T*H-1
    int lane = threadIdx.x & 31;
    int t = w >> 4;
    int hd = w & 15;

    const float* base = g_qkv + (size_t)t * HD3 + hd * HDIM;
    float c = g_cos[t * 32 + lane];
    float s = g_sin[t * 32 + lane];

    size_t qk_off = ((size_t)hd * T_SEQ + t) * HDIM;
    __nv_bfloat16 hi, lo;

    // ---- Q ----
    {
        float x1 = base[lane];
        float x2 = base[32 + lane];
        float ss = x1 * x1 + x2 * x2;
#pragma unroll
        for (int off = 16; off; off >>= 1) ss += __shfl_xor_sync(0xffffffffu, ss, off);
        float rn = 1.0f / sqrtf(ss * (1.0f / 64.0f) + RMS_EPS);
        x1 *= rn; x2 *= rn;
        float y1 = x1 * c + x2 * s;
        float y2 = x2 * c - x1 * s;
        split_bf(y1, hi, lo);
        g_Qh[qk_off + lane] = hi; g_Ql[qk_off + lane] = lo;
        split_bf(y2, hi, lo);
        g_Qh[qk_off + 32 + lane] = hi; g_Ql[qk_off + 32 + lane] = lo;
    }
    // ---- K ----
    {
        float x1 = base[1024 + lane];
        float x2 = base[1024 + 32 + lane];
        float ss = x1 * x1 + x2 * x2;
#pragma unroll
        for (int off = 16; off; off >>= 1) ss += __shfl_xor_sync(0xffffffffu, ss, off);
        float rn = 1.0f / sqrtf(ss * (1.0f / 64.0f) + RMS_EPS);
        x1 *= rn; x2 *= rn;
        float y1 = x1 * c + x2 * s;
        float y2 = x2 * c - x1 * s;
        split_bf(y1, hi, lo);
        g_Kh[qk_off + lane] = hi; g_Kl[qk_off + lane] = lo;
        split_bf(y2, hi, lo);
        g_Kh[qk_off + 32 + lane] = hi; g_Kl[qk_off + 32 + lane] = lo;
    }
    // ---- V (transposed [h][d][t]) ----
    {
        float lam = lambdas[0];
        float v1 = lam * base[2048 + lane];
        float v2 = lam * base[2048 + 32 + lane];
        size_t vo1 = ((size_t)hd * HDIM + lane) * T_SEQ + t;
        size_t vo2 = ((size_t)hd * HDIM + 32 + lane) * T_SEQ + t;
        split_bf(v1, hi, lo);
        g_Vth[vo1] = hi; g_Vtl[vo1] = lo;
        split_bf(v2, hi, lo);
        g_Vth[vo2] = hi; g_Vtl[vo2] = lo;
    }
}

// ===========================================================================
// Causal flash attention on tensor cores (mma.sync bf16-split).
// CTA: 128 q rows x 64 kv step; 8 warps, m16 per warp; D=64.
// ===========================================================================
#define FLS 72    // smem row stride in halves (144B -> conflict-free ldmatrix)

__global__ void __launch_bounds__(256, 1) flash_mma_kernel() {
    __shared__ __align__(16) __nv_bfloat16 sK[2][64 * FLS];   // K hi/lo [kv][d]
    __shared__ __align__(16) __nv_bfloat16 sV[2][64 * FLS];   // Vt hi/lo [d][kv]

    int qb = blockIdx.x;       // 0..31
    int hd = blockIdx.y;       // head
    int tid = threadIdx.x;
    int wid = tid >> 5;
    int lane = tid & 31;
    int g = lane >> 2;
    int tig = lane & 3;
    int qbase = qb * 128;
    int r0 = qbase + wid * 16 + g;       // absolute q row (fragment row g)
    int r1 = r0 + 8;                     // fragment row g+8
    const float SCL = 0.125f * 1.44269504088896340736f;   // 1/8 * log2(e)

    const __nv_bfloat16* Qh_g = g_Qh + ((size_t)hd * T_SEQ + qbase) * HDIM;
    const __nv_bfloat16* Ql_g = g_Ql + ((size_t)hd * T_SEQ + qbase) * HDIM;
    const __nv_bfloat16* Kh_g = g_Kh + (size_t)hd * T_SEQ * HDIM;
    const __nv_bfloat16* Kl_g = g_Kl + (size_t)hd * T_SEQ * HDIM;
    const __nv_bfloat16* Vth_g = g_Vth + (size_t)hd * HDIM * T_SEQ;
    const __nv_bfloat16* Vtl_g = g_Vtl + (size_t)hd * HDIM * T_SEQ;

    // ldmatrix addressing (identical scheme to the proven GEMM kernel)
    int a_off = (wid * 16 + (lane & 15)) * FLS + (lane >> 4) * 8;   // A frags (Q)
    int b_row = (lane & 7) + ((lane >> 4) & 1) * 8;                 // B frags
    int b_koff = ((lane >> 3) & 1) * 8;

    __nv_bfloat16* stage = &sK[0][0];    // 128*FLS halves spans sK[0..1]

    // ---- Stage Q and load fragments into registers ----
    uint32_t qh[4][4], ql[4][4];
#pragma unroll
    for (int i = 0; i < 4; i++) {
        int idx = tid + 256 * i;          // 0..1023
        int r = idx >> 3, c8 = (idx & 7) * 8;
        *(uint4*)&stage[r * FLS + c8] = *(const uint4*)(Qh_g + (size_t)r * HDIM + c8);
    }
    __syncthreads();
#pragma unroll
    for (int ks = 0; ks < 4; ks++)
        LDSM4(qh[ks][0], qh[ks][1], qh[ks][2], qh[ks][3],
              smem_addr_u32(stage + a_off + ks * 16));
    __syncthreads();
#pragma unroll
    for (int i = 0; i < 4; i++) {
        int idx = tid + 256 * i;
        int r = idx >> 3, c8 = (idx & 7) * 8;
        *(uint4*)&stage[r * FLS + c8] = *(const uint4*)(Ql_g + (size_t)r * HDIM + c8);
    }
    __syncthreads();
#pragma unroll
    for (int ks = 0; ks < 4; ks++)
        LDSM4(ql[ks][0], ql[ks][1], ql[ks][2], ql[ks][3],
              smem_addr_u32(stage + a_off + ks * 16));

    // ---- Online softmax state & output accumulators ----
    float m0 = -1e30f, m1 = -1e30f, l0 = 0.0f, l1 = 0.0f;
    float acc_o[8][4];
#pragma unroll
    for (int j = 0; j < 8; j++)
#pragma unroll
        for (int r = 0; r < 4; r++) acc_o[j][r] = 0.0f;

    int ntiles = 2 * qb + 2;
    for (int kt = 0; kt < ntiles; kt++) {
        int kv0 = kt * 64;
        __syncthreads();
#pragma unroll
        for (int i = 0; i < 2; i++) {
            int idx = tid + 256 * i;      // 0..511
            int r = idx >> 3, c8 = (idx & 7) * 8;
            *(uint4*)&sK[0][r * FLS + c8] = *(const uint4*)(Kh_g + (size_t)(kv0 + r) * HDIM + c8);
            *(uint4*)&sK[1][r * FLS + c8] = *(const uint4*)(Kl_g + (size_t)(kv0 + r) * HDIM + c8);
            *(uint4*)&sV[0][r * FLS + c8] = *(const uint4*)(Vth_g + (size_t)r * T_SEQ + kv0 + c8);
            *(uint4*)&sV[1][r * FLS + c8] = *(const uint4*)(Vtl_g + (size_t)r * T_SEQ + kv0 + c8);
        }
        __syncthreads();

        if (kv0 > qbase + wid * 16 + 15) continue;   // tile fully above diagonal

        // ---- S = Q K^T (split: 3 MMAs) ----
        float acc_s[8][4];
#pragma unroll
        for (int j = 0; j < 8; j++)
#pragma unroll
            for (int r = 0; r < 4; r++) acc_s[j][r] = 0.0f;

#pragma unroll
        for (int g2 = 0; g2 < 4; g2++) {
            int roff = (b_row + g2 * 16) * FLS + b_koff;
#pragma unroll
            for (int ks = 0; ks < 4; ks++) {
                uint32_t bh0, bh1, bh2, bh3, bl0, bl1, bl2, bl3;
                LDSM4(bh0, bh1, bh2, bh3, smem_addr_u32(&sK[0][0] + roff + ks * 16));
                LDSM4(bl0, bl1, bl2, bl3, smem_addr_u32(&sK[1][0] + roff + ks * 16));
                MMA16816(acc_s[2 * g2], qh[ks][0], qh[ks][1], qh[ks][2], qh[ks][3], bh0, bh1);
                MMA16816(acc_s[2 * g2], qh[ks][0], qh[ks][1], qh[ks][2], qh[ks][3], bl0, bl1);
                MMA16816(acc_s[2 * g2], ql[ks][0], ql[ks][1], ql[ks][2], ql[ks][3], bh0, bh1);
                MMA16816(acc_s[2 * g2 + 1], qh[ks][0], qh[ks][1], qh[ks][2], qh[ks][3], bh2, bh3);
                MMA16816(acc_s[2 * g2 + 1], qh[ks][0], qh[ks][1], qh[ks][2], qh[ks][3], bl2, bl3);
                MMA16816(acc_s[2 * g2 + 1], ql[ks][0], ql[ks][1], ql[ks][2], ql[ks][3], bh2, bh3);
            }
        }

        // ---- scale, causal mask, row max ----
        float tm0 = -1e30f, tm1 = -1e30f;
#pragma unroll
        for (int j = 0; j < 8; j++) {
            int cc = kv0 + 8 * j + 2 * tig;
            float s0 = acc_s[j][0] * SCL; if (cc > r0) s0 = -1e30f;
            float s1 = acc_s[j][1] * SCL; if (cc + 1 > r0) s1 = -1e30f;
            float s2 = acc_s[j][2] * SCL; if (cc > r1) s2 = -1e30f;
            float s3 = acc_s[j][3] * SCL; if (cc + 1 > r1) s3 = -1e30f;
            acc_s[j][0] = s0; acc_s[j][1] = s1; acc_s[j][2] = s2; acc_s[j][3] = s3;
            tm0 = fmaxf(tm0, fmaxf(s0, s1));
            tm1 = fmaxf(tm1, fmaxf(s2, s3));
        }
        tm0 = fmaxf(tm0, __shfl_xor_sync(0xffffffffu, tm0, 1));
        tm0 = fmaxf(tm0, __shfl_xor_sync(0xffffffffu, tm0, 2));
        tm1 = fmaxf(tm1, __shfl_xor_sync(0xffffffffu, tm1, 1));
        tm1 = fmaxf(tm1, __shfl_xor_sync(0xffffffffu, tm1, 2));

        float nm0 = fmaxf(m0, tm0);
        float nm1 = fmaxf(m1, tm1);
        float f0 = exp2f(m0 - nm0);
        float f1 = exp2f(m1 - nm1);

        float ps0 = 0.0f, ps1 = 0.0f;
#pragma unroll
        for (int j = 0; j < 8; j++) {
            float p0 = exp2f(acc_s[j][0] - nm0);
            float p1 = exp2f(acc_s[j][1] - nm0);
            float p2 = exp2f(acc_s[j][2] - nm1);
            float p3 = exp2f(acc_s[j][3] - nm1);
            acc_s[j][0] = p0; acc_s[j][1] = p1; acc_s[j][2] = p2; acc_s[j][3] = p3;
            ps0 += p0 + p1; ps1 += p2 + p3;
        }
        l0 = l0 * f0 + ps0;
        l1 = l1 * f1 + ps1;
#pragma unroll
        for (int j = 0; j < 8; j++) {
            acc_o[j][0] *= f0; acc_o[j][1] *= f0;
            acc_o[j][2] *= f1; acc_o[j][3] *= f1;
        }
        m0 = nm0; m1 = nm1;

        // ---- pack P hi/lo A-fragments from accumulators ----
        uint32_t ph[4][4], pl[4][4];
#pragma unroll
        for (int kc = 0; kc < 4; kc++) {
            __nv_bfloat16 ha, la, hb, lb;
            split_bf(acc_s[2 * kc][0], ha, la); split_bf(acc_s[2 * kc][1], hb, lb);
            ph[kc][0] = pack_bf2(ha, hb); pl[kc][0] = pack_bf2(la, lb);
            split_bf(acc_s[2 * kc][2], ha, la); split_bf(acc_s[2 * kc][3], hb, lb);
            ph[kc][1] = pack_bf2(ha, hb); pl[kc][1] = pack_bf2(la, lb);
            split_bf(acc_s[2 * kc + 1][0], ha, la); split_bf(acc_s[2 * kc + 1][1], hb, lb);
            ph[kc][2] = pack_bf2(ha, hb); pl[kc][2] = pack_bf2(la, lb);
            split_bf(acc_s[2 * kc + 1][2], ha, la); split_bf(acc_s[2 * kc + 1][3], hb, lb);
            ph[kc][3] = pack_bf2(ha, hb); pl[kc][3] = pack_bf2(la, lb);
        }

        // ---- O += P V (split: 3 MMAs) ----
#pragma unroll
        for (int g2 = 0; g2 < 4; g2++) {
            int roff = (b_row + g2 * 16) * FLS + b_koff;
#pragma unroll
            for (int kc = 0; kc < 4; kc++) {
                uint32_t vh0, vh1, vh2, vh3, vl0, vl1, vl2, vl3;
                LDSM4(vh0, vh1, vh2, vh3, smem_addr_u32(&sV[0][0] + roff + kc * 16));
                LDSM4(vl0, vl1, vl2, vl3, smem_addr_u32(&sV[1][0] + roff + kc * 16));
                MMA16816(acc_o[2 * g2], ph[kc][0], ph[kc][1], ph[kc][2], ph[kc][3], vh0, vh1);
                MMA16816(acc_o[2 * g2], pl[kc][0], pl[kc][1], pl[kc][2], pl[kc][3], vh0, vh1);
                MMA16816(acc_o[2 * g2], ph[kc][0], ph[kc][1], ph[kc][2], ph[kc][3], vl0, vl1);
                MMA16816(acc_o[2 * g2 + 1], ph[kc][0], ph[kc][1], ph[kc][2], ph[kc][3], vh2, vh3);
                MMA16816(acc_o[2 * g2 + 1], pl[kc][0], pl[kc][1], pl[kc][2], pl[kc][3], vh2, vh3);
                MMA16816(acc_o[2 * g2 + 1], ph[kc][0], ph[kc][1], ph[kc][2], ph[kc][3], vl2, vl3);
            }
        }
    }

    // ---- finalize: reduce l across quad, normalize, store ----
    l0 += __shfl_xor_sync(0xffffffffu, l0, 1);
    l0 += __shfl_xor_sync(0xffffffffu, l0, 2);
    l1 += __shfl_xor_sync(0xffffffffu, l1, 1);
    l1 += __shfl_xor_sync(0xffffffffu, l1, 2);
    float inv0 = 1.0f / l0;
    float inv1 = 1.0f / l1;

#pragma unroll
    for (int j = 0; j < 8; j++) {
        size_t base = (size_t)r0 * DIM + hd * HDIM + 8 * j + 2 * tig;
        *(float2*)&g_Y[base] = make_float2(acc_o[j][0] * inv0, acc_o[j][1] * inv0);
        *(float2*)&g_Y[base + (size_t)8 * DIM] = make_float2(acc_o[j][2] * inv1, acc_o[j][3] * inv1);
    }
}

// ---------------------------------------------------------------------------
// Launch
// ---------------------------------------------------------------------------
extern "C" void kernel_launch(void* const* d_in, const int* in_sizes, int n_in,
                              void* d_out, int out_size)
{
    const float* x = (const float*)d_in[0];        // [1,4096,1024]
    const float* qkv_w = (const float*)d_in[1];    // [3072,1024]
    const float* lambdas = (const float*)d_in[2];  // [1]
    const float* proj_w = (const float*)d_in[3];   // [1024,1024]
    float* out = (float*)d_out;

    float *p_qkv, *p_Y, *p_cos, *p_sin;
    cudaGetSymbolAddress((void**)&p_qkv, g_qkv);
    cudaGetSymbolAddress((void**)&p_Y, g_Y);
    cudaGetSymbolAddress((void**)&p_cos, g_cos);
    cudaGetSymbolAddress((void**)&p_sin, g_sin);

    // 0) RoPE tables
    rope_tables_kernel<<<T_SEQ, 32>>>(p_cos, p_sin);

    // 1) QKV GEMM (mma.sync bf16-split): [4096,1024] x [3072,1024]^T
    {
        dim3 grid(HD3 / 128, T_SEQ / 128);
        gemm_mma_kernel<<<grid, 256>>>(x, qkv_w, p_qkv, HD3, DIM);
    }

    // 2) RMSNorm + RoPE + lambda*v, emit bf16 hi/lo splits
    {
        int warps = T_SEQ * NHEAD;
        qkv_post_kernel<<<warps * 32 / 256, 256>>>(lambdas);
    }

    // 3) Causal flash attention (tensor cores)
    {
        dim3 grid(T_SEQ / 128, NHEAD);
        flash_mma_kernel<<<grid, 256>>>();
    }

    // 4) Proj GEMM (mma.sync bf16-split): [4096,1024] x [1024,1024]^T
    {
        dim3 grid(DIM / 128, T_SEQ / 128);
        gemm_mma_kernel<<<grid, 256>>>(p_Y, proj_w, out, DIM, DIM);
    }
}